// round 4
// baseline (speedup 1.0000x reference)
#include <cuda_runtime.h>
#include <cuda_bf16.h>
#include <cstdint>
#include <cfloat>
#include <math.h>

#define Bn 2
#define Ln 4096
#define Hn 8
#define Dn 64
#define NTOP 45
#define NSAMP 45
#define NCAND 128
#define BHn (Bn*Hn)
#define SPLITS 64
#define CHUNK (Ln/SPLITS)   /* 64 keys per split */

// ---------------- device scratch ----------------
__device__ float    g_M[BHn * Ln];
__device__ int      g_cand[BHn * NCAND];
__device__ float    g_Mex[BHn * NCAND];
__device__ int      g_top[BHn * NTOP];
__device__ unsigned g_is64;
__device__ unsigned g_Kbf[(size_t)Bn*Ln*Hn*Dn/2];        // bf16x2 copy of K, 8 MB
__device__ float    g_pl [BHn * NTOP * SPLITS];
__device__ float    g_pacc[(size_t)BHn * NTOP * SPLITS * Dn];

// ---------------- index dtype detection ----------------
__global__ void k_detect(const unsigned* __restrict__ raw) {
    unsigned v = 0;
    for (int i = 1 + 2*(int)threadIdx.x; i < Ln*NSAMP; i += 2*(int)blockDim.x)
        v |= raw[i];
    #pragma unroll
    for (int o = 16; o; o >>= 1) v |= __shfl_xor_sync(0xffffffffu, v, o);
    __shared__ unsigned s[8];
    if ((threadIdx.x & 31) == 0) s[threadIdx.x >> 5] = v;
    __syncthreads();
    if (threadIdx.x == 0) {
        unsigned t = 0;
        for (int i = 0; i < (int)(blockDim.x >> 5); i++) t |= s[i];
        g_is64 = (t == 0u) ? 1u : 0u;
    }
}

// ---------------- K -> bf16 copy ----------------
__global__ __launch_bounds__(256) void k_cvt(const float* __restrict__ k) {
    int i = blockIdx.x * 256 + threadIdx.x;      // i < Bn*Ln*Hn*Dn/4
    float4 f = ((const float4*)k)[i];
    __nv_bfloat162 b0 = __floats2bfloat162_rn(f.x, f.y);
    __nv_bfloat162 b1 = __floats2bfloat162_rn(f.z, f.w);
    g_Kbf[2*i]   = *(unsigned*)&b0;
    g_Kbf[2*i+1] = *(unsigned*)&b1;
}

// ---------------- stage 1: approx sampled scores from bf16 K ----------------
__global__ __launch_bounds__(256) void k_scoreM(const float* __restrict__ q,
                                                const unsigned* __restrict__ raw) {
    int w    = (blockIdx.x * 256 + threadIdx.x) >> 5;
    int lane = threadIdx.x & 31;
    int bh = w / Ln;
    int l  = w % Ln;
    int b = bh / Hn, h = bh % Hn;

    const float2 qv = *(const float2*)(q + (((size_t)b*Ln + l)*Hn + h)*Dn + 2*lane);

    int sh = (int)g_is64;
    const unsigned* ip = raw + ((size_t)(l * NSAMP) << sh);
    int i0 = (int)ip[(unsigned)lane << sh];
    int i1 = (lane < NSAMP - 32) ? (int)ip[(unsigned)(32 + lane) << sh] : 0;

    float mx = -FLT_MAX, sm = 0.f;
    #pragma unroll 9
    for (int s = 0; s < NSAMP; s++) {
        int id = __shfl_sync(0xffffffffu, (s < 32) ? i0 : i1, s & 31);
        unsigned kw = g_Kbf[(((size_t)b*Ln + id)*Hn + h)*(Dn/2) + lane];
        float2 kv = __bfloat1622float2(*(__nv_bfloat162*)&kw);
        float d2 = qv.x*kv.x + qv.y*kv.y;
        #pragma unroll
        for (int o = 16; o; o >>= 1) d2 += __shfl_xor_sync(0xffffffffu, d2, o);
        mx = fmaxf(mx, d2);
        sm += d2;
    }
    if (lane == 0) g_M[bh*Ln + l] = mx - sm * (1.0f / (float)Ln);
}

// ---------------- stage 2a: top-128 candidates via radix-256 select ----------------
__global__ __launch_bounds__(1024) void k_cand() {
    int bh  = blockIdx.x;
    int tid = threadIdx.x;

    __shared__ int bins[256];
    __shared__ int s_sel, s_need, s_out;

    unsigned r[4];
    #pragma unroll
    for (int i = 0; i < 4; i++) {
        unsigned u = __float_as_uint(g_M[bh*Ln + tid + i*1024]);
        r[i] = (u & 0x80000000u) ? ~u : (u | 0x80000000u);
    }

    unsigned prefix = 0;
    int need = NCAND;
    #pragma unroll
    for (int p = 0; p < 4; p++) {
        int shift = 24 - 8*p;
        unsigned pmask = (p == 0) ? 0u : (0xFFFFFFFFu << (32 - 8*p));
        if (tid < 256) bins[tid] = 0;
        __syncthreads();
        #pragma unroll
        for (int i = 0; i < 4; i++)
            if ((r[i] & pmask) == prefix)
                atomicAdd(&bins[(r[i] >> shift) & 255], 1);
        __syncthreads();
        if (tid == 0) {
            int c = 0, bb = 255;
            for (; bb > 0; bb--) { c += bins[bb]; if (c >= need) break; }
            if (c < need) { c += bins[0]; bb = 0; }
            s_sel  = bb;
            s_need = need - (c - bins[bb]);
        }
        __syncthreads();
        prefix |= ((unsigned)s_sel) << shift;
        need    = s_need;
        __syncthreads();
    }
    unsigned T = prefix;

    if (tid == 0) s_out = 0;
    __syncthreads();
    #pragma unroll
    for (int i = 0; i < 4; i++)
        if (r[i] > T) {
            int p = atomicAdd(&s_out, 1);
            g_cand[bh*NCAND + p] = tid + i*1024;
        }
    __syncthreads();
    #pragma unroll
    for (int i = 0; i < 4; i++)
        if (r[i] == T) {
            int p = atomicAdd(&s_out, 1);
            if (p < NCAND) g_cand[bh*NCAND + p] = tid + i*1024;
        }
}

// ---------------- stage 2b: exact fp32 rescore of the 128 candidates ----------------
__global__ __launch_bounds__(256) void k_rescore(const float* __restrict__ q,
                                                 const float* __restrict__ k,
                                                 const unsigned* __restrict__ raw) {
    int w    = (blockIdx.x * 256 + threadIdx.x) >> 5;   // < BHn*NCAND
    int lane = threadIdx.x & 31;
    int bh = w / NCAND;
    int c  = w % NCAND;
    int b = bh / Hn, h = bh % Hn;
    int l = g_cand[bh*NCAND + c];

    const float2 qv = *(const float2*)(q + (((size_t)b*Ln + l)*Hn + h)*Dn + 2*lane);

    int sh = (int)g_is64;
    const unsigned* ip = raw + ((size_t)(l * NSAMP) << sh);
    int i0 = (int)ip[(unsigned)lane << sh];
    int i1 = (lane < NSAMP - 32) ? (int)ip[(unsigned)(32 + lane) << sh] : 0;

    float mx = -FLT_MAX, sm = 0.f;
    #pragma unroll 9
    for (int s = 0; s < NSAMP; s++) {
        int id = __shfl_sync(0xffffffffu, (s < 32) ? i0 : i1, s & 31);
        float2 kv = *(const float2*)(k + (((size_t)b*Ln + id)*Hn + h)*Dn + 2*lane);
        float d2 = qv.x*kv.x + qv.y*kv.y;
        #pragma unroll
        for (int o = 16; o; o >>= 1) d2 += __shfl_xor_sync(0xffffffffu, d2, o);
        mx = fmaxf(mx, d2);
        sm += d2;
    }
    if (lane == 0) g_Mex[bh*NCAND + c] = mx - sm * (1.0f / (float)Ln);
}

// ---------------- stage 2c: exact top-45 of 128 (jax tie-break) ----------------
__global__ __launch_bounds__(NCAND) void k_sel45() {
    int bh  = blockIdx.x;
    int tid = threadIdx.x;
    __shared__ unsigned long long comp[NCAND];

    int idx = g_cand[bh*NCAND + tid];
    unsigned u = __float_as_uint(g_Mex[bh*NCAND + tid]);
    u = (u & 0x80000000u) ? ~u : (u | 0x80000000u);
    // value desc, index asc: larger composite = better
    comp[tid] = ((unsigned long long)u << 32) | (unsigned)(Ln - 1 - idx);
    __syncthreads();

    unsigned long long mine = comp[tid];
    int rank = 0;
    #pragma unroll 16
    for (int j = 0; j < NCAND; j++) rank += (comp[j] > mine);
    if (rank < NTOP) g_top[bh*NTOP + rank] = idx;
}

// ---------------- stage 3: split-KV attention partials ----------------
__global__ __launch_bounds__(256) void k_attn(const float* __restrict__ q,
                                              const float* __restrict__ k,
                                              const float* __restrict__ v) {
    int split = blockIdx.x;
    int bh    = blockIdx.y;
    int b = bh / Hn, h = bh % Hn;
    int tid = threadIdx.x, warp = tid >> 5, lane = tid & 31;

    __shared__ float2 Kt2[32 * 65];
    __shared__ float2 Vs2[64 * 32];
    __shared__ float  Qs[48 * 64];

    int base_l = split * CHUNK;
    for (int e = tid; e < CHUNK * (Dn/4); e += 256) {
        int row  = e >> 4;
        int col4 = e & 15;
        size_t g = (((size_t)b*Ln + base_l + row)*Hn + h)*Dn;
        float4 kf = *((const float4*)(k + g) + col4);
        float4 vf = *((const float4*)(v + g) + col4);
        ((float4*)Vs2)[e] = vf;
        int dp0 = col4 * 2;
        Kt2[dp0*65 + row]     = make_float2(kf.x, kf.y);
        Kt2[(dp0+1)*65 + row] = make_float2(kf.z, kf.w);
    }
    for (int e = tid; e < 48 * (Dn/4); e += 256) {
        int u  = e >> 4;
        int c4 = e & 15;
        float4 qf = make_float4(0.f, 0.f, 0.f, 0.f);
        if (u < NTOP) {
            int lq = g_top[bh*NTOP + u];
            qf = *((const float4*)(q + (((size_t)b*Ln + lq)*Hn + h)*Dn) + c4);
        }
        ((float4*)Qs)[e] = qf;
    }
    __syncthreads();

    int nq = 5 + (warp < (NTOP % 8) ? 1 : 0);

    float s0[6], s1[6];
    #pragma unroll
    for (int i = 0; i < 6; i++) { s0[i] = 0.f; s1[i] = 0.f; }

    #pragma unroll
    for (int dp = 0; dp < 32; dp++) {
        float2 k0 = Kt2[dp*65 + lane];
        float2 k1 = Kt2[dp*65 + 32 + lane];
        #pragma unroll
        for (int i = 0; i < 6; i++) {
            float2 qd = *(const float2*)&Qs[(warp + 8*i)*64 + 2*dp];
            s0[i] += qd.x*k0.x + qd.y*k0.y;
            s1[i] += qd.x*k1.x + qd.y*k1.y;
        }
    }

    const float scale = 0.125f;
    #pragma unroll
    for (int i = 0; i < 6; i++) {
        float p0 = __expf(s0[i] * scale);
        float p1 = __expf(s1[i] * scale);
        float ls = p0 + p1;
        #pragma unroll
        for (int o = 16; o; o >>= 1) ls += __shfl_xor_sync(0xffffffffu, ls, o);

        float2 acc = make_float2(0.f, 0.f);
        #pragma unroll
        for (int j = 0; j < 32; j++) {
            float p = __shfl_sync(0xffffffffu, p0, j);
            float2 vv = Vs2[j*32 + lane];
            acc.x += p*vv.x; acc.y += p*vv.y;
        }
        #pragma unroll
        for (int j = 0; j < 32; j++) {
            float p = __shfl_sync(0xffffffffu, p1, j);
            float2 vv = Vs2[(j+32)*32 + lane];
            acc.x += p*vv.x; acc.y += p*vv.y;
        }

        if (i < nq) {
            int u = warp + 8*i;
            size_t pidx = (size_t)(bh*NTOP + u)*SPLITS + split;
            if (lane == 0) g_pl[pidx] = ls;
            *(float2*)(g_pacc + pidx*Dn + 2*lane) = acc;
        }
    }
}

// ---------------- stage 4: combine splits + scatter ----------------
__global__ __launch_bounds__(64) void k_combine(float* __restrict__ out) {
    int gi = blockIdx.x;
    int bh = gi / NTOP, u = gi % NTOP;
    int b = bh / Hn, h = bh % Hn;
    int tid = threadIdx.x;

    __shared__ float lsh[SPLITS];
    lsh[tid] = g_pl[(size_t)gi*SPLITS + tid];
    __syncthreads();

    float den = 0.f;
    #pragma unroll
    for (int s = 0; s < SPLITS; s++) den += lsh[s];

    float acc = 0.f;
    #pragma unroll 8
    for (int s = 0; s < SPLITS; s++)
        acc += g_pacc[((size_t)gi*SPLITS + s)*Dn + tid];

    int lq = g_top[bh*NTOP + u];
    out[(((size_t)b*Ln + lq)*Hn + h)*Dn + tid] = acc / den;
}

// ---------------- launch ----------------
extern "C" void kernel_launch(void* const* d_in, const int* in_sizes, int n_in,
                              void* d_out, int out_size) {
    const float* q = (const float*)d_in[0];
    const float* k = (const float*)d_in[1];
    const float* v = (const float*)d_in[2];
    const unsigned* idxraw = (const unsigned*)d_in[4];
    float* out = (float*)d_out;

    cudaMemsetAsync(d_out, 0, (size_t)out_size * sizeof(float));

    k_detect <<<1, 256>>>(idxraw);
    k_cvt    <<<(Bn*Ln*Hn*Dn/4)/256, 256>>>(k);
    k_scoreM <<<(BHn*Ln)/8, 256>>>(q, idxraw);
    k_cand   <<<BHn, 1024>>>();
    k_rescore<<<(BHn*NCAND)/8, 256>>>(q, k, idxraw);
    k_sel45  <<<BHn, NCAND>>>();

    dim3 g3(SPLITS, BHn);
    k_attn   <<<g3, 256>>>(q, k, v);
    k_combine<<<BHn*NTOP, 64>>>(out);
}

// round 5
// speedup vs baseline: 1.1312x; 1.1312x over previous
#include <cuda_runtime.h>
#include <cuda_bf16.h>
#include <cstdint>
#include <cfloat>
#include <math.h>

#define Bn 2
#define Ln 4096
#define Hn 8
#define Dn 64
#define NTOP 45
#define NSAMP 45
#define NCAND 128
#define BHn (Bn*Hn)
#define SPLITS 32
#define CHUNK (Ln/SPLITS)   /* 128 keys per block, 2 sub-chunks of 64 */
#define SUB 64

// ---------------- device scratch ----------------
__device__ float    g_M[BHn * Ln];
__device__ int      g_cand[BHn * NCAND];
__device__ float    g_Mex[BHn * NCAND];
__device__ int      g_top[BHn * NTOP];
__device__ unsigned g_anyodd;
__device__ unsigned g_Kbf[(size_t)Bn*Ln*Hn*Dn/2];        // bf16x2 copy of K, 8 MB
__device__ float    g_pl [BHn * NTOP * SPLITS];
__device__ float    g_pacc[(size_t)BHn * NTOP * SPLITS * Dn];  // 5.9 MB

// ---------------- index dtype detection (parallel) ----------------
// int64 indices < 4096 => every odd 32-bit word is zero. OR them all.
__global__ __launch_bounds__(256) void k_detect(const unsigned* __restrict__ raw) {
    unsigned v = 0;
    for (int i = 1 + 2*(int)(blockIdx.x*256 + threadIdx.x); i < Ln*NSAMP; i += 2*90*256)
        v |= raw[i];
    #pragma unroll
    for (int o = 16; o; o >>= 1) v |= __shfl_xor_sync(0xffffffffu, v, o);
    if ((threadIdx.x & 31) == 0 && v) atomicOr(&g_anyodd, v);
}

// ---------------- K -> bf16 copy ----------------
__global__ __launch_bounds__(256) void k_cvt(const float* __restrict__ k) {
    int i = blockIdx.x * 256 + threadIdx.x;
    float4 f = ((const float4*)k)[i];
    __nv_bfloat162 b0 = __floats2bfloat162_rn(f.x, f.y);
    __nv_bfloat162 b1 = __floats2bfloat162_rn(f.z, f.w);
    g_Kbf[2*i]   = *(unsigned*)&b0;
    g_Kbf[2*i+1] = *(unsigned*)&b1;
}

// ---------------- stage 1: approx sampled scores from bf16 K ----------------
__global__ __launch_bounds__(256) void k_scoreM(const float* __restrict__ q,
                                                const unsigned* __restrict__ raw) {
    int w    = (blockIdx.x * 256 + threadIdx.x) >> 5;
    int lane = threadIdx.x & 31;
    int bh = w / Ln;
    int l  = w % Ln;
    int b = bh / Hn, h = bh % Hn;

    const float2 qv = *(const float2*)(q + (((size_t)b*Ln + l)*Hn + h)*Dn + 2*lane);

    int sh = (g_anyodd == 0u) ? 1 : 0;
    const unsigned* ip = raw + ((size_t)(l * NSAMP) << sh);
    int i0 = (int)ip[(unsigned)lane << sh];
    int i1 = (lane < NSAMP - 32) ? (int)ip[(unsigned)(32 + lane) << sh] : 0;

    float mx = -FLT_MAX, sm = 0.f;
    #pragma unroll 9
    for (int s = 0; s < NSAMP; s++) {
        int id = __shfl_sync(0xffffffffu, (s < 32) ? i0 : i1, s & 31);
        unsigned kw = g_Kbf[(((size_t)b*Ln + id)*Hn + h)*(Dn/2) + lane];
        float2 kv = __bfloat1622float2(*(__nv_bfloat162*)&kw);
        float d2 = qv.x*kv.x + qv.y*kv.y;
        #pragma unroll
        for (int o = 16; o; o >>= 1) d2 += __shfl_xor_sync(0xffffffffu, d2, o);
        mx = fmaxf(mx, d2);
        sm += d2;
    }
    if (lane == 0) g_M[bh*Ln + l] = mx - sm * (1.0f / (float)Ln);
}

// ---------------- stage 2a: top-128 candidates via radix-256 select ----------------
// Serial bin scan replaced by warp-0 shuffle suffix-scan (8 bins/lane).
__global__ __launch_bounds__(1024) void k_cand() {
    int bh  = blockIdx.x;
    int tid = threadIdx.x;
    int lane = tid & 31;

    __shared__ int bins[256];
    __shared__ int ssum[256];
    __shared__ int s_sel, s_need, s_out;

    unsigned r[4];
    #pragma unroll
    for (int i = 0; i < 4; i++) {
        unsigned u = __float_as_uint(g_M[bh*Ln + tid + i*1024]);
        r[i] = (u & 0x80000000u) ? ~u : (u | 0x80000000u);
    }

    unsigned prefix = 0;
    int need = NCAND;
    #pragma unroll
    for (int p = 0; p < 4; p++) {
        int shift = 24 - 8*p;
        unsigned pmask = (p == 0) ? 0u : (0xFFFFFFFFu << (32 - 8*p));
        if (tid < 256) bins[tid] = 0;
        __syncthreads();
        #pragma unroll
        for (int i = 0; i < 4; i++)
            if ((r[i] & pmask) == prefix)
                atomicAdd(&bins[(r[i] >> shift) & 255], 1);
        __syncthreads();
        // warp 0: suffix sums over 256 bins
        if (tid < 32) {
            int x[8], loc = 0;
            #pragma unroll
            for (int j = 0; j < 8; j++) { x[j] = bins[lane*8 + j]; loc += x[j]; }
            int suf = loc;
            #pragma unroll
            for (int o = 1; o < 32; o <<= 1) {
                int t = __shfl_down_sync(0xffffffffu, suf, o);
                if (lane + o < 32) suf += t;
            }
            int run = suf - loc;          // strictly-greater lanes
            #pragma unroll
            for (int j = 7; j >= 0; j--) { run += x[j]; ssum[lane*8 + j] = run; }
        }
        __syncthreads();
        if (tid < 256) {
            int above = (tid < 255) ? ssum[tid + 1] : 0;
            if (ssum[tid] >= need && above < need) {
                s_sel  = tid;
                s_need = need - above;
            }
        }
        __syncthreads();
        prefix |= ((unsigned)s_sel) << shift;
        need    = s_need;
        __syncthreads();
    }
    unsigned T = prefix;

    if (tid == 0) s_out = 0;
    __syncthreads();
    #pragma unroll
    for (int i = 0; i < 4; i++)
        if (r[i] > T) {
            int p = atomicAdd(&s_out, 1);
            g_cand[bh*NCAND + p] = tid + i*1024;
        }
    __syncthreads();
    #pragma unroll
    for (int i = 0; i < 4; i++)
        if (r[i] == T) {
            int p = atomicAdd(&s_out, 1);
            if (p < NCAND) g_cand[bh*NCAND + p] = tid + i*1024;
        }
}

// ---------------- stage 2b: exact fp32 rescore of the 128 candidates ----------------
__global__ __launch_bounds__(256) void k_rescore(const float* __restrict__ q,
                                                 const float* __restrict__ k,
                                                 const unsigned* __restrict__ raw) {
    int w    = (blockIdx.x * 256 + threadIdx.x) >> 5;
    int lane = threadIdx.x & 31;
    int bh = w / NCAND;
    int c  = w % NCAND;
    int b = bh / Hn, h = bh % Hn;
    int l = g_cand[bh*NCAND + c];

    const float2 qv = *(const float2*)(q + (((size_t)b*Ln + l)*Hn + h)*Dn + 2*lane);

    int sh = (g_anyodd == 0u) ? 1 : 0;
    const unsigned* ip = raw + ((size_t)(l * NSAMP) << sh);
    int i0 = (int)ip[(unsigned)lane << sh];
    int i1 = (lane < NSAMP - 32) ? (int)ip[(unsigned)(32 + lane) << sh] : 0;

    float mx = -FLT_MAX, sm = 0.f;
    #pragma unroll 9
    for (int s = 0; s < NSAMP; s++) {
        int id = __shfl_sync(0xffffffffu, (s < 32) ? i0 : i1, s & 31);
        float2 kv = *(const float2*)(k + (((size_t)b*Ln + id)*Hn + h)*Dn + 2*lane);
        float d2 = qv.x*kv.x + qv.y*kv.y;
        #pragma unroll
        for (int o = 16; o; o >>= 1) d2 += __shfl_xor_sync(0xffffffffu, d2, o);
        mx = fmaxf(mx, d2);
        sm += d2;
    }
    if (lane == 0) g_Mex[bh*NCAND + c] = mx - sm * (1.0f / (float)Ln);
}

// ---------------- stage 2c: exact top-45 of 128 (jax tie-break) ----------------
__global__ __launch_bounds__(NCAND) void k_sel45() {
    int bh  = blockIdx.x;
    int tid = threadIdx.x;
    __shared__ unsigned long long comp[NCAND];

    int idx = g_cand[bh*NCAND + tid];
    unsigned u = __float_as_uint(g_Mex[bh*NCAND + tid]);
    u = (u & 0x80000000u) ? ~u : (u | 0x80000000u);
    comp[tid] = ((unsigned long long)u << 32) | (unsigned)(Ln - 1 - idx);
    __syncthreads();

    unsigned long long mine = comp[tid];
    int rank = 0;
    #pragma unroll 16
    for (int j = 0; j < NCAND; j++) rank += (comp[j] > mine);
    if (rank < NTOP) g_top[bh*NTOP + rank] = idx;
}

// ---------------- stage 3: split-KV attention partials ----------------
// 128 keys per block in 2 sub-chunks of 64. QK: K transposed in smem.
// AV reordered: j outer, V row hoisted, p's staged in per-warp smem (aliasing
// the Kt2 buffer, guarded by a barrier) and read as float4 broadcasts.
__global__ __launch_bounds__(256) void k_attn(const float* __restrict__ q,
                                              const float* __restrict__ k,
                                              const float* __restrict__ v) {
    int split = blockIdx.x;
    int bh    = blockIdx.y;
    int b = bh / Hn, h = bh % Hn;
    int tid = threadIdx.x, warp = tid >> 5, lane = tid & 31;

    __shared__ __align__(16) float2 Kt2[32 * 65];   // 16640 B; reused as ps[8][64][8]
    __shared__ float2 Vs2[64 * 32];                 // 16384 B
    __shared__ float  Qs[48 * 64];                  // 12288 B
    float* ps = (float*)Kt2;

    // stage Q once per block
    for (int e = tid; e < 48 * (Dn/4); e += 256) {
        int u  = e >> 4;
        int c4 = e & 15;
        float4 qf = make_float4(0.f, 0.f, 0.f, 0.f);
        if (u < NTOP) {
            int lq = g_top[bh*NTOP + u];
            qf = *((const float4*)(q + (((size_t)b*Ln + lq)*Hn + h)*Dn) + c4);
        }
        ((float4*)Qs)[e] = qf;
    }

    int nq = 5 + (warp < (NTOP % 8) ? 1 : 0);
    float2 acc[6];
    float  lt[6];
    #pragma unroll
    for (int i = 0; i < 6; i++) { acc[i] = make_float2(0.f, 0.f); lt[i] = 0.f; }

    for (int c = 0; c < 2; c++) {
        if (c) __syncthreads();           // all warps done with ps/Vs of prev chunk
        int base_l = split * CHUNK + c * SUB;
        for (int e = tid; e < SUB * (Dn/4); e += 256) {
            int row  = e >> 4;
            int col4 = e & 15;
            size_t g = (((size_t)b*Ln + base_l + row)*Hn + h)*Dn;
            float4 kf = *((const float4*)(k + g) + col4);
            float4 vf = *((const float4*)(v + g) + col4);
            ((float4*)Vs2)[e] = vf;
            int dp0 = col4 * 2;
            Kt2[dp0*65 + row]     = make_float2(kf.x, kf.y);
            Kt2[(dp0+1)*65 + row] = make_float2(kf.z, kf.w);
        }
        __syncthreads();                  // K/V staged (covers Q stage on c=0)

        // ---- QK: lane owns keys (lane, lane+32) ----
        float s0[6], s1[6];
        #pragma unroll
        for (int i = 0; i < 6; i++) { s0[i] = 0.f; s1[i] = 0.f; }
        #pragma unroll
        for (int dp = 0; dp < 32; dp++) {
            float2 k0 = Kt2[dp*65 + lane];
            float2 k1 = Kt2[dp*65 + 32 + lane];
            #pragma unroll
            for (int i = 0; i < 6; i++) {
                float2 qd = *(const float2*)&Qs[(warp + 8*i)*64 + 2*dp];
                s0[i] += qd.x*k0.x + qd.y*k0.y;
                s1[i] += qd.x*k1.x + qd.y*k1.y;
            }
        }
        __syncthreads();                  // Kt2 fully consumed; safe to alias as ps

        // ---- exp + stage p's ----
        const float scale = 0.125f;
        float* pw = ps + warp * 512;      // [64 keys][8 floats]
        #pragma unroll
        for (int i = 0; i < 6; i++) {
            float p0 = __expf(s0[i] * scale);
            float p1 = __expf(s1[i] * scale);
            pw[lane*8 + i]      = p0;
            pw[(lane+32)*8 + i] = p1;
            float ls = p0 + p1;
            #pragma unroll
            for (int o = 16; o; o >>= 1) ls += __shfl_xor_sync(0xffffffffu, ls, o);
            lt[i] += ls;
        }
        __syncwarp();

        // ---- AV: j outer, V hoisted, p broadcast ----
        #pragma unroll 4
        for (int j = 0; j < SUB; j++) {
            float2 vv = Vs2[j*32 + lane];
            float4 pA = *(const float4*)&pw[j*8];
            float2 pB = *(const float2*)&pw[j*8 + 4];
            acc[0].x += pA.x*vv.x; acc[0].y += pA.x*vv.y;
            acc[1].x += pA.y*vv.x; acc[1].y += pA.y*vv.y;
            acc[2].x += pA.z*vv.x; acc[2].y += pA.z*vv.y;
            acc[3].x += pA.w*vv.x; acc[3].y += pA.w*vv.y;
            acc[4].x += pB.x*vv.x; acc[4].y += pB.x*vv.y;
            acc[5].x += pB.y*vv.x; acc[5].y += pB.y*vv.y;
        }
    }

    for (int i = 0; i < nq; i++) {
        int u = warp + 8*i;
        size_t pidx = (size_t)(bh*NTOP + u)*SPLITS + split;
        if (lane == 0) g_pl[pidx] = lt[i];
        *(float2*)(g_pacc + pidx*Dn + 2*lane) = acc[i];
    }
}

// ---------------- stage 4: combine splits + scatter ----------------
__global__ __launch_bounds__(256) void k_combine(float* __restrict__ out) {
    int gi = blockIdx.x;                 // bh*NTOP + u
    int bh = gi / NTOP, u = gi % NTOP;
    int b = bh / Hn, h = bh % Hn;
    int tid = threadIdx.x;
    int grp = tid >> 6, d = tid & 63;

    __shared__ float lsh[SPLITS];
    __shared__ float part[4][64];

    if (tid < SPLITS) lsh[tid] = g_pl[(size_t)gi*SPLITS + tid];
    __syncthreads();

    float a = 0.f;
    #pragma unroll
    for (int s8 = 0; s8 < 8; s8++)
        a += g_pacc[((size_t)gi*SPLITS + grp*8 + s8)*Dn + d];
    part[grp][d] = a;
    __syncthreads();

    if (grp == 0) {
        float den = 0.f;
        #pragma unroll
        for (int s = 0; s < SPLITS; s++) den += lsh[s];
        float tot = part[0][d] + part[1][d] + part[2][d] + part[3][d];
        int lq = g_top[bh*NTOP + u];
        out[(((size_t)b*Ln + lq)*Hn + h)*Dn + d] = tot / den;
    }
}

// ---------------- launch ----------------
extern "C" void kernel_launch(void* const* d_in, const int* in_sizes, int n_in,
                              void* d_out, int out_size) {
    const float* q = (const float*)d_in[0];
    const float* k = (const float*)d_in[1];
    const float* v = (const float*)d_in[2];
    const unsigned* idxraw = (const unsigned*)d_in[4];
    float* out = (float*)d_out;

    cudaMemsetAsync(d_out, 0, (size_t)out_size * sizeof(float));

    void* p_anyodd = nullptr;
    cudaGetSymbolAddress(&p_anyodd, g_anyodd);
    cudaMemsetAsync(p_anyodd, 0, sizeof(unsigned));

    k_detect <<<90, 256>>>(idxraw);
    k_cvt    <<<(Bn*Ln*Hn*Dn/4)/256, 256>>>(k);
    k_scoreM <<<(BHn*Ln)/8, 256>>>(q, idxraw);
    k_cand   <<<BHn, 1024>>>();
    k_rescore<<<(BHn*NCAND)/8, 256>>>(q, k, idxraw);
    k_sel45  <<<BHn, NCAND>>>();

    dim3 g3(SPLITS, BHn);
    k_attn   <<<g3, 256>>>(q, k, v);
    k_combine<<<BHn*NTOP, 256>>>(out);
}

// round 6
// speedup vs baseline: 1.7916x; 1.5838x over previous
#include <cuda_runtime.h>
#include <cuda_bf16.h>
#include <cstdint>
#include <cfloat>
#include <math.h>

#define Bn 2
#define Ln 4096
#define Hn 8
#define Dn 64
#define NTOP 45
#define NSAMP 45
#define NCAND 128
#define BHn (Bn*Hn)
#define SPLITS 32
#define CHUNK (Ln/SPLITS)   /* 128 keys per block, 2 sub-chunks of 64 */
#define SUB 64

// ---------------- device scratch ----------------
__device__ float    g_M[BHn * Ln];
__device__ int      g_cand[BHn * NCAND];
__device__ float    g_Mex[BHn * NCAND];
__device__ int      g_top[BHn * NTOP];
__device__ unsigned g_anyodd;
__device__ unsigned g_Kbf[(size_t)Bn*Ln*Hn*Dn/2];        // bf16x2 copy of K, 8 MB
__device__ float    g_pl [BHn * NTOP * SPLITS];
__device__ float    g_pacc[(size_t)BHn * NTOP * SPLITS * Dn];

// ---------------- tiny zero kernel (also pads launch order for ncu) ----------------
__global__ void k_zero() { g_anyodd = 0u; }

// ---------------- K -> bf16 copy ----------------
__global__ __launch_bounds__(256) void k_cvt(const float* __restrict__ k) {
    int i = blockIdx.x * 256 + threadIdx.x;
    float4 f = ((const float4*)k)[i];
    __nv_bfloat162 b0 = __floats2bfloat162_rn(f.x, f.y);
    __nv_bfloat162 b1 = __floats2bfloat162_rn(f.z, f.w);
    g_Kbf[2*i]   = *(unsigned*)&b0;
    g_Kbf[2*i+1] = *(unsigned*)&b1;
}

// ---------------- index dtype detection (parallel) ----------------
__global__ __launch_bounds__(256) void k_detect(const unsigned* __restrict__ raw) {
    unsigned v = 0;
    for (int i = 1 + 2*(int)(blockIdx.x*256 + threadIdx.x); i < Ln*NSAMP; i += 2*90*256)
        v |= raw[i];
    #pragma unroll
    for (int o = 16; o; o >>= 1) v |= __shfl_xor_sync(0xffffffffu, v, o);
    if ((threadIdx.x & 31) == 0 && v) atomicOr(&g_anyodd, v);
}

// ---------------- stage 1: approx sampled scores from bf16 K ----------------
// 8 lanes per sample, 4 samples in flight per warp. Lane loads uint4 = 8 bf16
// of its sample's key row; 3-shfl reduce within the 8-lane group; 2-shfl
// combine across groups at the end. 12 iterations cover 45 samples (+3 masked).
__global__ __launch_bounds__(256) void k_scoreM(const float* __restrict__ q,
                                                const unsigned* __restrict__ raw) {
    int w    = (blockIdx.x * 256 + threadIdx.x) >> 5;   // < BHn*Ln
    int lane = threadIdx.x & 31;
    int grp  = lane >> 3;          // 0..3 : sample slot
    int sub  = lane & 7;           // 0..7 : 8-bf16 slice within row
    int bh = w / Ln;
    int l  = w % Ln;
    int b = bh / Hn, h = bh % Hn;

    const float4* qp = (const float4*)(q + (((size_t)b*Ln + l)*Hn + h)*Dn + sub*8);
    float4 qa = qp[0], qb = qp[1];

    int sh = (g_anyodd == 0u) ? 1 : 0;
    const unsigned* ip = raw + ((size_t)(l * NSAMP) << sh);
    int i0 = (int)ip[(unsigned)lane << sh];
    int i1 = (lane < NSAMP - 32) ? (int)ip[(unsigned)(32 + lane) << sh] : 0;

    const unsigned* kbase = g_Kbf + ((size_t)b*Ln*Hn + h)*(Dn/2);

    float mx = -FLT_MAX, sm = 0.f;
    #pragma unroll
    for (int t = 0; t < 12; t++) {
        int s  = 4*t + grp;
        int id = (4*t < 32) ? __shfl_sync(0xffffffffu, i0, s)
                            : __shfl_sync(0xffffffffu, i1, s - 32);
        uint4 kw = *((const uint4*)(kbase + (size_t)id*(Hn*Dn/2)) + sub);
        float2 k0 = __bfloat1622float2(*(__nv_bfloat162*)&kw.x);
        float2 k1 = __bfloat1622float2(*(__nv_bfloat162*)&kw.y);
        float2 k2 = __bfloat1622float2(*(__nv_bfloat162*)&kw.z);
        float2 k3 = __bfloat1622float2(*(__nv_bfloat162*)&kw.w);
        float d = qa.x*k0.x + qa.y*k0.y + qa.z*k1.x + qa.w*k1.y
                + qb.x*k2.x + qb.y*k2.y + qb.z*k3.x + qb.w*k3.y;
        #pragma unroll
        for (int o = 1; o < 8; o <<= 1) d += __shfl_xor_sync(0xffffffffu, d, o);
        if (s < NSAMP) { mx = fmaxf(mx, d); sm += d; }
    }
    #pragma unroll
    for (int o = 8; o < 32; o <<= 1) {
        mx = fmaxf(mx, __shfl_xor_sync(0xffffffffu, mx, o));
        sm += __shfl_xor_sync(0xffffffffu, sm, o);
    }
    if (lane == 0) g_M[bh*Ln + l] = mx - sm * (1.0f / (float)Ln);
}

// ---------------- stage 2a: top-128 candidates via radix-256 select ----------------
__global__ __launch_bounds__(1024) void k_cand() {
    int bh  = blockIdx.x;
    int tid = threadIdx.x;
    int lane = tid & 31;

    __shared__ int bins[256];
    __shared__ int ssum[256];
    __shared__ int s_sel, s_need, s_out;

    unsigned r[4];
    #pragma unroll
    for (int i = 0; i < 4; i++) {
        unsigned u = __float_as_uint(g_M[bh*Ln + tid + i*1024]);
        r[i] = (u & 0x80000000u) ? ~u : (u | 0x80000000u);
    }

    unsigned prefix = 0;
    int need = NCAND;
    #pragma unroll
    for (int p = 0; p < 4; p++) {
        int shift = 24 - 8*p;
        unsigned pmask = (p == 0) ? 0u : (0xFFFFFFFFu << (32 - 8*p));
        if (tid < 256) bins[tid] = 0;
        __syncthreads();
        #pragma unroll
        for (int i = 0; i < 4; i++)
            if ((r[i] & pmask) == prefix)
                atomicAdd(&bins[(r[i] >> shift) & 255], 1);
        __syncthreads();
        if (tid < 32) {
            int x[8], loc = 0;
            #pragma unroll
            for (int j = 0; j < 8; j++) { x[j] = bins[lane*8 + j]; loc += x[j]; }
            int suf = loc;
            #pragma unroll
            for (int o = 1; o < 32; o <<= 1) {
                int t = __shfl_down_sync(0xffffffffu, suf, o);
                if (lane + o < 32) suf += t;
            }
            int run = suf - loc;
            #pragma unroll
            for (int j = 7; j >= 0; j--) { run += x[j]; ssum[lane*8 + j] = run; }
        }
        __syncthreads();
        if (tid < 256) {
            int above = (tid < 255) ? ssum[tid + 1] : 0;
            if (ssum[tid] >= need && above < need) {
                s_sel  = tid;
                s_need = need - above;
            }
        }
        __syncthreads();
        prefix |= ((unsigned)s_sel) << shift;
        need    = s_need;
        __syncthreads();
    }
    unsigned T = prefix;

    if (tid == 0) s_out = 0;
    __syncthreads();
    #pragma unroll
    for (int i = 0; i < 4; i++)
        if (r[i] > T) {
            int p = atomicAdd(&s_out, 1);
            g_cand[bh*NCAND + p] = tid + i*1024;
        }
    __syncthreads();
    #pragma unroll
    for (int i = 0; i < 4; i++)
        if (r[i] == T) {
            int p = atomicAdd(&s_out, 1);
            if (p < NCAND) g_cand[bh*NCAND + p] = tid + i*1024;
        }
}

// ---------------- stage 2b: exact fp32 rescore of the 128 candidates ----------------
__global__ __launch_bounds__(256) void k_rescore(const float* __restrict__ q,
                                                 const float* __restrict__ k,
                                                 const unsigned* __restrict__ raw) {
    int w    = (blockIdx.x * 256 + threadIdx.x) >> 5;
    int lane = threadIdx.x & 31;
    int bh = w / NCAND;
    int c  = w % NCAND;
    int b = bh / Hn, h = bh % Hn;
    int l = g_cand[bh*NCAND + c];

    const float2 qv = *(const float2*)(q + (((size_t)b*Ln + l)*Hn + h)*Dn + 2*lane);

    int sh = (g_anyodd == 0u) ? 1 : 0;
    const unsigned* ip = raw + ((size_t)(l * NSAMP) << sh);
    int i0 = (int)ip[(unsigned)lane << sh];
    int i1 = (lane < NSAMP - 32) ? (int)ip[(unsigned)(32 + lane) << sh] : 0;

    float mx = -FLT_MAX, sm = 0.f;
    #pragma unroll 9
    for (int s = 0; s < NSAMP; s++) {
        int id = __shfl_sync(0xffffffffu, (s < 32) ? i0 : i1, s & 31);
        float2 kv = *(const float2*)(k + (((size_t)b*Ln + id)*Hn + h)*Dn + 2*lane);
        float d2 = qv.x*kv.x + qv.y*kv.y;
        #pragma unroll
        for (int o = 16; o; o >>= 1) d2 += __shfl_xor_sync(0xffffffffu, d2, o);
        mx = fmaxf(mx, d2);
        sm += d2;
    }
    if (lane == 0) g_Mex[bh*NCAND + c] = mx - sm * (1.0f / (float)Ln);
}

// ---------------- stage 2c: exact top-45 of 128 (jax tie-break) ----------------
__global__ __launch_bounds__(NCAND) void k_sel45() {
    int bh  = blockIdx.x;
    int tid = threadIdx.x;
    __shared__ unsigned long long comp[NCAND];

    int idx = g_cand[bh*NCAND + tid];
    unsigned u = __float_as_uint(g_Mex[bh*NCAND + tid]);
    u = (u & 0x80000000u) ? ~u : (u | 0x80000000u);
    comp[tid] = ((unsigned long long)u << 32) | (unsigned)(Ln - 1 - idx);
    __syncthreads();

    unsigned long long mine = comp[tid];
    int rank = 0;
    #pragma unroll 16
    for (int j = 0; j < NCAND; j++) rank += (comp[j] > mine);
    if (rank < NTOP) g_top[bh*NTOP + rank] = idx;
}

// ---------------- stage 3: split-KV attention partials ----------------
__global__ __launch_bounds__(256) void k_attn(const float* __restrict__ q,
                                              const float* __restrict__ k,
                                              const float* __restrict__ v) {
    int split = blockIdx.x;
    int bh    = blockIdx.y;
    int b = bh / Hn, h = bh % Hn;
    int tid = threadIdx.x, warp = tid >> 5, lane = tid & 31;

    __shared__ __align__(16) float2 Kt2[32 * 65];   // reused as ps[8][64][8]
    __shared__ float2 Vs2[64 * 32];
    __shared__ float  Qs[48 * 64];
    float* ps = (float*)Kt2;

    for (int e = tid; e < 48 * (Dn/4); e += 256) {
        int u  = e >> 4;
        int c4 = e & 15;
        float4 qf = make_float4(0.f, 0.f, 0.f, 0.f);
        if (u < NTOP) {
            int lq = g_top[bh*NTOP + u];
            qf = *((const float4*)(q + (((size_t)b*Ln + lq)*Hn + h)*Dn) + c4);
        }
        ((float4*)Qs)[e] = qf;
    }

    int nq = 5 + (warp < (NTOP % 8) ? 1 : 0);
    float2 acc[6];
    float  lt[6];
    #pragma unroll
    for (int i = 0; i < 6; i++) { acc[i] = make_float2(0.f, 0.f); lt[i] = 0.f; }

    for (int c = 0; c < 2; c++) {
        if (c) __syncthreads();
        int base_l = split * CHUNK + c * SUB;
        for (int e = tid; e < SUB * (Dn/4); e += 256) {
            int row  = e >> 4;
            int col4 = e & 15;
            size_t g = (((size_t)b*Ln + base_l + row)*Hn + h)*Dn;
            float4 kf = *((const float4*)(k + g) + col4);
            float4 vf = *((const float4*)(v + g) + col4);
            ((float4*)Vs2)[e] = vf;
            int dp0 = col4 * 2;
            Kt2[dp0*65 + row]     = make_float2(kf.x, kf.y);
            Kt2[(dp0+1)*65 + row] = make_float2(kf.z, kf.w);
        }
        __syncthreads();

        float s0[6], s1[6];
        #pragma unroll
        for (int i = 0; i < 6; i++) { s0[i] = 0.f; s1[i] = 0.f; }
        #pragma unroll
        for (int dp = 0; dp < 32; dp++) {
            float2 k0 = Kt2[dp*65 + lane];
            float2 k1 = Kt2[dp*65 + 32 + lane];
            #pragma unroll
            for (int i = 0; i < 6; i++) {
                float2 qd = *(const float2*)&Qs[(warp + 8*i)*64 + 2*dp];
                s0[i] += qd.x*k0.x + qd.y*k0.y;
                s1[i] += qd.x*k1.x + qd.y*k1.y;
            }
        }
        __syncthreads();

        const float scale = 0.125f;
        float* pw = ps + warp * 512;
        #pragma unroll
        for (int i = 0; i < 6; i++) {
            float p0 = __expf(s0[i] * scale);
            float p1 = __expf(s1[i] * scale);
            pw[lane*8 + i]      = p0;
            pw[(lane+32)*8 + i] = p1;
            float ls = p0 + p1;
            #pragma unroll
            for (int o = 16; o; o >>= 1) ls += __shfl_xor_sync(0xffffffffu, ls, o);
            lt[i] += ls;
        }
        __syncwarp();

        #pragma unroll 4
        for (int j = 0; j < SUB; j++) {
            float2 vv = Vs2[j*32 + lane];
            float4 pA = *(const float4*)&pw[j*8];
            float2 pB = *(const float2*)&pw[j*8 + 4];
            acc[0].x += pA.x*vv.x; acc[0].y += pA.x*vv.y;
            acc[1].x += pA.y*vv.x; acc[1].y += pA.y*vv.y;
            acc[2].x += pA.z*vv.x; acc[2].y += pA.z*vv.y;
            acc[3].x += pA.w*vv.x; acc[3].y += pA.w*vv.y;
            acc[4].x += pB.x*vv.x; acc[4].y += pB.x*vv.y;
            acc[5].x += pB.y*vv.x; acc[5].y += pB.y*vv.y;
        }
    }

    for (int i = 0; i < nq; i++) {
        int u = warp + 8*i;
        size_t pidx = (size_t)(bh*NTOP + u)*SPLITS + split;
        if (lane == 0) g_pl[pidx] = lt[i];
        *(float2*)(g_pacc + pidx*Dn + 2*lane) = acc[i];
    }
}

// ---------------- stage 4: combine splits + scatter ----------------
__global__ __launch_bounds__(256) void k_combine(float* __restrict__ out) {
    int gi = blockIdx.x;
    int bh = gi / NTOP, u = gi % NTOP;
    int b = bh / Hn, h = bh % Hn;
    int tid = threadIdx.x;
    int grp = tid >> 6, d = tid & 63;

    __shared__ float lsh[SPLITS];
    __shared__ float part[4][64];

    if (tid < SPLITS) lsh[tid] = g_pl[(size_t)gi*SPLITS + tid];
    __syncthreads();

    float a = 0.f;
    #pragma unroll
    for (int s8 = 0; s8 < 8; s8++)
        a += g_pacc[((size_t)gi*SPLITS + grp*8 + s8)*Dn + d];
    part[grp][d] = a;
    __syncthreads();

    if (grp == 0) {
        float den = 0.f;
        #pragma unroll
        for (int s = 0; s < SPLITS; s++) den += lsh[s];
        float tot = part[0][d] + part[1][d] + part[2][d] + part[3][d];
        int lq = g_top[bh*NTOP + u];
        out[(((size_t)b*Ln + lq)*Hn + h)*Dn + d] = tot / den;
    }
}

// ---------------- launch ----------------
extern "C" void kernel_launch(void* const* d_in, const int* in_sizes, int n_in,
                              void* d_out, int out_size) {
    const float* q = (const float*)d_in[0];
    const float* k = (const float*)d_in[1];
    const float* v = (const float*)d_in[2];
    const unsigned* idxraw = (const unsigned*)d_in[4];
    float* out = (float*)d_out;

    cudaMemsetAsync(d_out, 0, (size_t)out_size * sizeof(float));

    k_zero   <<<1, 1>>>();                              // kernel #1
    k_cvt    <<<(Bn*Ln*Hn*Dn/4)/256, 256>>>(k);         // kernel #2
    k_detect <<<90, 256>>>(idxraw);                     // kernel #3
    k_scoreM <<<(BHn*Ln)/8, 256>>>(q, idxraw);          // kernel #4  (ncu target)
    k_cand   <<<BHn, 1024>>>();
    k_rescore<<<(BHn*NCAND)/8, 256>>>(q, k, idxraw);
    k_sel45  <<<BHn, NCAND>>>();

    dim3 g3(SPLITS, BHn);
    k_attn   <<<g3, 256>>>(q, k, v);
    k_combine<<<BHn*NTOP, 256>>>(out);
}